// round 14
// baseline (speedup 1.0000x reference)
#include <cuda_runtime.h>
#include <cstddef>

// HBV fused time-scan — 3-ROLE WARP-SPECIALIZED PIPELINE.
// Wall-clock law (measured R6/R10/R12): time = 730 * cycles/step of the
// slowest-role warp. So the critical warp (soil recurrence, irreducible
// ~56cyc MUFU chain) is stripped to ONLY that chain. Block = 384 threads:
//   warps 0-3  : SNOW    (chunk e)   x-loads + snow ladder -> rt,PET rings + SWE
//   warps 4-7  : SOIL    (chunk e-1) SM recurrence only -> SMn ring
//   warps 8-11 : ROUTING (chunk e-2) rech/ET/SM' recompute + routing -> Q,AET
// One warp of each role per SMSP (wid%4). 730 = 73 chunks of 10, no peeling.

#define NSTEP  730
#define NGRID  10000
#define PFD    10
#define NCHUNK 73
#define NEPOCH (NCHUNK + 2)
#define ROWX   (NGRID*3)
#define NEARZERO 1e-5f

__device__ __forceinline__ float fast_exp2(float v) {
    float r;
    asm("ex2.approx.ftz.f32 %0, %1;" : "=f"(r) : "f"(v));
    return r;   // MUFU.EX2
}

__global__ __launch_bounds__(384, 1)
void hbv_kernel(const float* __restrict__ x,
                const float* __restrict__ params,
                float* __restrict__ out)
{
    const int  tid   = threadIdx.x;
    const int  role  = tid >> 7;            // 0 snow, 1 soil, 2 routing
    const int  l     = tid & 127;           // cell slot within CTA
    const int  cell  = blockIdx.x * 128 + l;
    const bool valid = (cell < NGRID);
    const int  cellc = valid ? cell : (NGRID - 1);

    // rings: rt/PET live 2 extra epochs (soil @e+1, routing @e+2) -> depth 3
    //        SMn lives 1 extra epoch (routing @e+1)               -> depth 2
    __shared__ float RT [3][PFD][128];
    __shared__ float PE [3][PFD][128];
    __shared__ float SMN[2][PFD][128];

    const float* p = params + ((size_t)(NSTEP - 1) * NGRID + (size_t)cellc) * 12;
    const float BETA    = 1.0f   + p[0]  * 5.0f;
    const float FC      = 50.0f  + p[1]  * 950.0f;
    const float K0      = 0.05f  + p[2]  * 0.85f;
    const float K1      = 0.01f  + p[3]  * 0.49f;
    const float K2      = 0.001f + p[4]  * 0.199f;
    const float LP      = 0.2f   + p[5]  * 0.8f;
    const float PERCmax =          p[6]  * 10.0f;
    const float UZL     =          p[7]  * 100.0f;
    const float TT      = -2.5f  + p[8]  * 5.0f;
    const float CFMAX   = 0.5f   + p[9]  * 9.5f;
    const float CFR     =          p[10] * 0.1f;
    const float CWH     =          p[11] * 0.2f;

    const float invLPFC     = 1.0f / (LP * FC);
    const float betaLgInvFC = BETA * __log2f(1.0f / FC);  // (SM/FC)^B = exp2(B*lgSM + this)
    const float K1m         = 1.0f - K1;
    const float K01         = K0 * K1m;                    // Q0+Q1 = K01*u + K1*s1

    const size_t n = (size_t)NSTEP * NGRID;

    // ---------------- role-private state ----------------
    // snow
    float SNOWPACK = 0.001f, MELTWATER = 0.001f;
    float bP[PFD], bT[PFD], bE[PFD], nP[PFD], nT[PFD], nE[PFD];
    const float* xb = x + (size_t)cellc * 3;
    float* sp = out + 2 * n + cellc;               // SWE
    // soil
    float SM = 0.001f;
    // routing
    float SMprev = 0.001f, SUZ = 0.001f, SLZ = 0.001f;
    float* qp = out + cellc;                       // Qsim
    float* ap = out + n + cellc;                   // AET

    // prologue: snow loads chunk 0 inputs (rows 0..9)
    if (role == 0) {
#pragma unroll
        for (int j = 0; j < PFD; ++j) {
            bP[j] = xb[j * ROWX];
            bT[j] = xb[j * ROWX + 1];
            bE[j] = xb[j * ROWX + 2];
        }
    }
    __syncthreads();   // (harmless; keeps all threads aligned before epoch 0)

    for (int e = 0; e < NEPOCH; ++e) {
        if (role == 0) {
            // ---------------- SNOW: chunk e ----------------
            if (e < NCHUNK) {
                if (e < NCHUNK - 1) {              // prefetch chunk e+1
#pragma unroll
                    for (int j = 0; j < PFD; ++j) {
                        nP[j] = xb[(PFD + j) * ROWX];
                        nT[j] = xb[(PFD + j) * ROWX + 1];
                        nE[j] = xb[(PFD + j) * ROWX + 2];
                    }
                }
                const int rs = e % 3;
#pragma unroll
                for (int j = 0; j < PFD; ++j) {
                    const float Pt = bP[j], Tt = bT[j], Et = bE[j];
                    const float RAIN = (Tt >= TT) ? Pt : 0.0f;
                    const float m    = CFMAX * (Tt - TT);
                    const float sel  = (m >= 0.0f) ? m : (CFR * m);   // melt / -refreeze
                    const float SP1  = SNOWPACK + (Pt - RAIN);
                    const float nn   = fminf(fmaxf(sel, -MELTWATER), SP1);
                    SNOWPACK  = SP1 - nn;
                    MELTWATER = MELTWATER + nn;
                    const float tosoil = fmaxf(fmaf(-CWH, SNOWPACK, MELTWATER), 0.0f);
                    MELTWATER -= tosoil;
                    RT[rs][j][l] = RAIN + tosoil;
                    PE[rs][j][l] = Et;
                    if (valid) sp[j * NGRID] = SNOWPACK;
                }
#pragma unroll
                for (int j = 0; j < PFD; ++j) { bP[j]=nP[j]; bT[j]=nT[j]; bE[j]=nE[j]; }
                xb += PFD * ROWX;
                sp += PFD * NGRID;
            }
        } else if (role == 1) {
            // ---------------- SOIL: chunk e-1 (the pacer) ----------------
            if (e >= 1 && e < NCHUNK + 1) {
                const int rs = (e - 1) % 3;
                const int ws = (e - 1) % 2;
#pragma unroll
                for (int j = 0; j < PFD; ++j) {
                    const float rt   = RT[rs][j][l];
                    const float PETv = PE[rs][j][l];
                    const float c1   = PETv * invLPFC;
                    const float lg   = __log2f(SM);
                    const float sw   = fast_exp2(fmaf(BETA, lg, betaLgInvFC));
                    const float a    = SM + rt;
                    // min(sw,1) folded: a - rt*min(sw,1) = max(fma(-rt,sw,a), SM)
                    const float SMn  = fmaxf(fmaf(-rt, sw, a), SM);
                    SM = fmaxf(fmaxf(fmaf(-c1, SMn, SMn), SMn - PETv), NEARZERO);
                    SMN[ws][j][l] = SMn;
                }
            }
        } else {
            // ---------------- ROUTING: chunk e-2 ----------------
            if (e >= 2) {
                const int c  = e - 2;
                const int rs = c % 3;
                const int ss = c % 2;
#pragma unroll
                for (int j = 0; j < PFD; ++j) {
                    const float SMn  = SMN[ss][j][l];
                    const float rt   = RT[rs][j][l];
                    const float PETv = PE[rs][j][l];
                    const float c1   = PETv * invLPFC;
                    const float a    = SMprev + rt;
                    const float rex  = (a - SMn) + fmaxf(SMn - FC, 0.0f); // rech+excess
                    const float ET   = fminf(fminf(SMn * c1, PETv), SMn);
                    SMprev = fmaxf(fmaxf(fmaf(-c1, SMn, SMn), SMn - PETv), NEARZERO);
                    const float SUZa = SUZ + rex;
                    const float PERC = fminf(SUZa, PERCmax);
                    const float s1   = SUZa - PERC;
                    const float u    = fmaxf(s1 - UZL, 0.0f);
                    const float t1   = K01 * u;
                    const float Q01  = fmaf(K1, s1, t1);
                    SUZ = fmaf(K1m, s1, -t1);
                    SLZ += PERC;
                    const float Q2 = K2 * SLZ;
                    SLZ -= Q2;
                    if (valid) { qp[j * NGRID] = Q01 + Q2; ap[j * NGRID] = ET; }
                }
                qp += PFD * NGRID;
                ap += PFD * NGRID;
            }
        }
        __syncthreads();
    }
}

extern "C" void kernel_launch(void* const* d_in, const int* in_sizes, int n_in,
                              void* d_out, int out_size)
{
    const float* x      = (const float*)d_in[0];
    const float* params = (const float*)d_in[1];
    float* out          = (float*)d_out;

    const int blocks = (NGRID + 127) / 128;   // 79 CTAs x 384 threads
    hbv_kernel<<<blocks, 384>>>(x, params, out);
}